// round 11
// baseline (speedup 1.0000x reference)
#include <cuda_runtime.h>
#include <cuda_bf16.h>

#define HEADS 4
#define DHEAD 32
#define HID 128
#define CIN 64
#define NPOS 4096
#define NSPLIT 4
#define CHUNK (NPOS / NSPLIT) /* 1024 */
#define KT 64                 /* keys per smem tile */
#define NTILES (CHUNK / KT)   /* 16 */
#define L2E 1.4426950408889634f

typedef unsigned int uint32;

// ---- device scratch ----
__device__ __align__(16) __nv_bfloat16 g_qtb[HEADS * NPOS * DHEAD]; // [h][n][d], scaled
__device__ __align__(16) __nv_bfloat16 g_ktb[HEADS * NPOS * DHEAD]; // [h][n][d]
__device__ __align__(16) __nv_bfloat16 g_vtb[HEADS * DHEAD * NPOS]; // [h][d][n] (transposed!)
__device__ float g_pm[HEADS * NPOS * NSPLIT];
__device__ float g_pl[HEADS * NPOS * NSPLIT];
__device__ __align__(16) float g_pacc[HEADS * NPOS * NSPLIT * DHEAD];
__device__ __align__(16) float g_o[HID * NPOS];                     // attention out fp32 [c][n]

// m16n8k16 bf16 MMA, fp32 accum, D==C in-place
__device__ __forceinline__ void mma16816(float* d, const uint32* a, uint32 b0, uint32 b1)
{
    asm volatile(
        "mma.sync.aligned.m16n8k16.row.col.f32.bf16.bf16.f32 "
        "{%0,%1,%2,%3},{%4,%5,%6,%7},{%8,%9},{%0,%1,%2,%3};"
        : "+f"(d[0]), "+f"(d[1]), "+f"(d[2]), "+f"(d[3])
        : "r"(a[0]), "r"(a[1]), "r"(a[2]), "r"(a[3]), "r"(b0), "r"(b1));
}

__device__ __forceinline__ uint32 pk2(float lo, float hi)
{
    __nv_bfloat162 t = __floats2bfloat162_rn(lo, hi);
    return *(uint32*)&t;
}

// ============================================================
// Kernel 1: QKV = w_qkv @ x (384x64 * 64x4096), fp32 math, bf16 stores.
// Q,K -> [h][n][32]; V -> [h][d][n] (transposed for PV MMA B-operand).
// ============================================================
__global__ void qkv_kernel(const float* __restrict__ x, const float* __restrict__ w)
{
    int n = blockIdx.x * 128 + threadIdx.x;
    int og = blockIdx.y * 8;

    __shared__ float ws[8 * 64];
    for (int idx = threadIdx.x; idx < 8 * 64; idx += 128)
        ws[idx] = w[og * 64 + idx];
    __syncthreads();

    float acc[8];
#pragma unroll
    for (int k = 0; k < 8; k++) acc[k] = 0.f;

#pragma unroll 4
    for (int c = 0; c < CIN; c++) {
        float xv = x[c * NPOS + n];
#pragma unroll
        for (int k = 0; k < 8; k++) acc[k] += ws[k * 64 + c] * xv;
    }

    int seg = og >> 7;          // 0=q 1=k 2=v
    int oo = og & 127;
    int h = oo >> 5, d0 = oo & 31;

    if (seg < 2) {
        float scale = (seg == 0) ? 0.17677669529663687f : 1.f;  // 32^-0.5 on Q
        __nv_bfloat162 h0 = __floats2bfloat162_rn(acc[0] * scale, acc[1] * scale);
        __nv_bfloat162 h1 = __floats2bfloat162_rn(acc[2] * scale, acc[3] * scale);
        __nv_bfloat162 h2 = __floats2bfloat162_rn(acc[4] * scale, acc[5] * scale);
        __nv_bfloat162 h3 = __floats2bfloat162_rn(acc[6] * scale, acc[7] * scale);
        uint4 pk;
        pk.x = *(uint32*)&h0; pk.y = *(uint32*)&h1;
        pk.z = *(uint32*)&h2; pk.w = *(uint32*)&h3;
        __nv_bfloat16* base = (seg == 0 ? g_qtb : g_ktb) + (size_t)(h * NPOS + n) * DHEAD + d0;
        *(uint4*)base = pk;
    } else {
#pragma unroll
        for (int k = 0; k < 8; k++)
            g_vtb[(size_t)(h * DHEAD + d0 + k) * NPOS + n] = __float2bfloat16(acc[k]);
    }
}

// ============================================================
// Kernel 2: tensor-core flash attention (bf16 mma.sync, fp32 accum).
// grid 512: bx = h(4) x split(4) x qblk(32). Block 256 = 8 warps,
// each warp owns 16 queries, loops CHUNK keys in 64-key SMEM tiles.
// ============================================================
__global__ void __launch_bounds__(256) flash_kernel()
{
    __shared__ __nv_bfloat16 sK[KT * 40];      // [64 keys][32 d], rows padded to 80B
    __shared__ __nv_bfloat16 sVt[DHEAD * 72];  // [32 d][64 keys], rows padded to 144B
    uint32* sKu = (uint32*)sK;
    uint32* sVu = (uint32*)sVt;

    int bx = blockIdx.x;
    int qblk = bx & 31, split = (bx >> 5) & 3, h = bx >> 7;
    int tid = threadIdx.x, w = tid >> 5, lane = tid & 31;
    int g = lane >> 2, tg = lane & 3;
    int q0 = qblk * 128 + w * 16;

    uint32 qa[2][4];
    {
        const uint32* Qb = (const uint32*)g_qtb + (size_t)(h * NPOS + q0) * 16;
#pragma unroll
        for (int ks = 0; ks < 2; ks++) {
            qa[ks][0] = Qb[g * 16 + tg + 8 * ks];
            qa[ks][1] = Qb[(g + 8) * 16 + tg + 8 * ks];
            qa[ks][2] = Qb[g * 16 + tg + 4 + 8 * ks];
            qa[ks][3] = Qb[(g + 8) * 16 + tg + 4 + 8 * ks];
        }
    }

    float o[4][4];
#pragma unroll
    for (int a = 0; a < 4; a++)
#pragma unroll
        for (int b = 0; b < 4; b++) o[a][b] = 0.f;
    float m0 = -1e30f, m1 = -1e30f, l0 = 0.f, l1 = 0.f;

    const uint32* Kg = (const uint32*)g_ktb + (size_t)(h * NPOS + split * CHUNK) * 16;
    const uint32* Vg = (const uint32*)g_vtb + (size_t)(h * DHEAD) * (NPOS / 2) + split * (CHUNK / 2);

    for (int tile = 0; tile < NTILES; tile++) {
        __syncthreads();
#pragma unroll
        for (int it = 0; it < 4; it++) {
            int idx = tid + it * 256;
            int row = idx >> 4, c = idx & 15;
            sKu[row * 20 + c] = Kg[(size_t)(tile * 64 + row) * 16 + c];
        }
#pragma unroll
        for (int it = 0; it < 4; it++) {
            int idx = tid + it * 256;
            int row = idx >> 5, c = idx & 31;
            sVu[row * 36 + c] = Vg[(size_t)row * (NPOS / 2) + tile * 32 + c];
        }
        __syncthreads();

#pragma unroll
        for (int kt = 0; kt < 4; kt++) {
            float s[2][4];
#pragma unroll
            for (int nt = 0; nt < 2; nt++)
#pragma unroll
                for (int c = 0; c < 4; c++) s[nt][c] = 0.f;

#pragma unroll
            for (int ks = 0; ks < 2; ks++) {
#pragma unroll
                for (int nt = 0; nt < 2; nt++) {
                    int krow = kt * 16 + nt * 8 + g;
                    uint32 b0 = sKu[krow * 20 + tg + 8 * ks];
                    uint32 b1 = sKu[krow * 20 + tg + 4 + 8 * ks];
                    mma16816(s[nt], qa[ks], b0, b1);
                }
            }

            float tm0 = fmaxf(fmaxf(s[0][0], s[0][1]), fmaxf(s[1][0], s[1][1]));
            float tm1 = fmaxf(fmaxf(s[0][2], s[0][3]), fmaxf(s[1][2], s[1][3]));
            tm0 = fmaxf(tm0, __shfl_xor_sync(0xffffffffu, tm0, 1));
            tm0 = fmaxf(tm0, __shfl_xor_sync(0xffffffffu, tm0, 2));
            tm1 = fmaxf(tm1, __shfl_xor_sync(0xffffffffu, tm1, 1));
            tm1 = fmaxf(tm1, __shfl_xor_sync(0xffffffffu, tm1, 2));
            float nm0 = fmaxf(m0, tm0), nm1 = fmaxf(m1, tm1);
            float c0 = exp2f((m0 - nm0) * L2E);
            float c1 = exp2f((m1 - nm1) * L2E);
            m0 = nm0; m1 = nm1;

            float p00 = exp2f((s[0][0] - nm0) * L2E);
            float p01 = exp2f((s[0][1] - nm0) * L2E);
            float p10 = exp2f((s[1][0] - nm0) * L2E);
            float p11 = exp2f((s[1][1] - nm0) * L2E);
            float p02 = exp2f((s[0][2] - nm1) * L2E);
            float p03 = exp2f((s[0][3] - nm1) * L2E);
            float p12 = exp2f((s[1][2] - nm1) * L2E);
            float p13 = exp2f((s[1][3] - nm1) * L2E);

            l0 = l0 * c0 + ((p00 + p01) + (p10 + p11));
            l1 = l1 * c1 + ((p02 + p03) + (p12 + p13));

#pragma unroll
            for (int nt = 0; nt < 4; nt++) {
                o[nt][0] *= c0; o[nt][1] *= c0;
                o[nt][2] *= c1; o[nt][3] *= c1;
            }

            uint32 pa[4];
            pa[0] = pk2(p00, p01);
            pa[1] = pk2(p02, p03);
            pa[2] = pk2(p10, p11);
            pa[3] = pk2(p12, p13);

#pragma unroll
            for (int nt = 0; nt < 4; nt++) {
                int vrow = nt * 8 + g;
                uint32 b0 = sVu[vrow * 36 + kt * 8 + tg];
                uint32 b1 = sVu[vrow * 36 + kt * 8 + tg + 4];
                mma16816(o[nt], pa, b0, b1);
            }
        }
    }

    l0 += __shfl_xor_sync(0xffffffffu, l0, 1);
    l0 += __shfl_xor_sync(0xffffffffu, l0, 2);
    l1 += __shfl_xor_sync(0xffffffffu, l1, 1);
    l1 += __shfl_xor_sync(0xffffffffu, l1, 2);

    int qg0 = h * NPOS + q0 + g;
    int qg1 = qg0 + 8;
    int pi0 = qg0 * NSPLIT + split;
    int pi1 = qg1 * NSPLIT + split;
    g_pm[pi0] = m0; g_pl[pi0] = l0;
    g_pm[pi1] = m1; g_pl[pi1] = l1;

    float2* P0 = (float2*)(g_pacc + (size_t)pi0 * 32);
    float2* P1 = (float2*)(g_pacc + (size_t)pi1 * 32);
#pragma unroll
    for (int nt = 0; nt < 4; nt++) {
        P0[nt * 4 + tg] = make_float2(o[nt][0], o[nt][1]);
        P1[nt * 4 + tg] = make_float2(o[nt][2], o[nt][3]);
    }
}

// ============================================================
// Kernel 3: combine NSPLIT partials per (h,i); write O in [c][n] layout
// ============================================================
__global__ void reduce_kernel()
{
    int idx = blockIdx.x * 128 + threadIdx.x;   // h*4096+i
    int h = idx >> 12;
    int i = idx & 4095;
    int base = idx * NSPLIT;

    float M = -1e30f;
#pragma unroll
    for (int s = 0; s < NSPLIT; s++) M = fmaxf(M, g_pm[base + s]);

    float L = 0.f;
    float num[32];
#pragma unroll
    for (int d = 0; d < 32; d++) num[d] = 0.f;

#pragma unroll
    for (int s = 0; s < NSPLIT; s++) {
        float es = exp2f((g_pm[base + s] - M) * L2E);
        L += g_pl[base + s] * es;
        const float4* pa = (const float4*)(g_pacc + (size_t)(base + s) * 32);
#pragma unroll
        for (int t = 0; t < 8; t++) {
            float4 a = pa[t];
            num[4 * t]     += a.x * es; num[4 * t + 1] += a.y * es;
            num[4 * t + 2] += a.z * es; num[4 * t + 3] += a.w * es;
        }
    }
    float inv = 1.f / L;
#pragma unroll
    for (int d = 0; d < 32; d++)
        g_o[(size_t)(h * DHEAD + d) * NPOS + i] = num[d] * inv;
}

// ============================================================
// Kernel 4: y = w_out @ O + b_out  (64x128 * 128x4096) — occupancy rework.
// 256 blocks x 256 threads. thread: o = tid&63, n-group = tid>>6 (4 n each).
// w_out staged transposed [c][o] in smem (conflict-free LDS: lanes = o).
// g_o read as broadcast float4 across the 32 lanes sharing an n-group.
// ============================================================
__global__ void __launch_bounds__(256) outproj_kernel(
    const float* __restrict__ w, const float* __restrict__ b, float* __restrict__ y)
{
    __shared__ float ws[HID * 64];   // [c][o] transposed, 32KB
    int tid = threadIdx.x;
    for (int idx = tid; idx < 64 * HID; idx += 256) {
        int o = idx >> 7, c = idx & 127;
        ws[c * 64 + o] = w[idx];
    }
    __syncthreads();

    int o = tid & 63;
    int n = blockIdx.x * 16 + (tid >> 6) * 4;

    float a0 = 0.f, a1 = 0.f, a2 = 0.f, a3 = 0.f;
#pragma unroll 8
    for (int c = 0; c < HID; c++) {
        float4 ov = *(const float4*)(g_o + (size_t)c * NPOS + n);
        float wv = ws[c * 64 + o];
        a0 += wv * ov.x; a1 += wv * ov.y; a2 += wv * ov.z; a3 += wv * ov.w;
    }
    float bb = b[o];
    float4 r = make_float4(a0 + bb, a1 + bb, a2 + bb, a3 + bb);
    *(float4*)(y + (size_t)o * NPOS + n) = r;
}

// ============================================================
extern "C" void kernel_launch(void* const* d_in, const int* in_sizes, int n_in,
                              void* d_out, int out_size)
{
    const float* x     = (const float*)d_in[0];
    const float* w_qkv = (const float*)d_in[1];
    const float* w_out = (const float*)d_in[2];
    const float* b_out = (const float*)d_in[3];
    float* y = (float*)d_out;

    qkv_kernel<<<dim3(NPOS / 128, 48), 128>>>(x, w_qkv);
    flash_kernel<<<512, 256>>>();
    reduce_kernel<<<128, 128>>>();
    outproj_kernel<<<256, 256>>>(w_out, b_out, y);
}

// round 12
// speedup vs baseline: 1.1338x; 1.1338x over previous
#include <cuda_runtime.h>
#include <cuda_bf16.h>

#define HEADS 4
#define DHEAD 32
#define HID 128
#define CIN 64
#define NPOS 4096
#define NSPLIT 4
#define CHUNK (NPOS / NSPLIT) /* 1024 */
#define KT 64                 /* keys per smem tile */
#define NTILES (CHUNK / KT)   /* 16 */
#define L2E 1.4426950408889634f

typedef unsigned int uint32;

// ---- device scratch ----
__device__ __align__(16) __nv_bfloat16 g_qtb[HEADS * NPOS * DHEAD]; // [h][n][d], scaled
__device__ __align__(16) __nv_bfloat16 g_ktb[HEADS * NPOS * DHEAD]; // [h][n][d]
__device__ __align__(16) __nv_bfloat16 g_vtb[HEADS * DHEAD * NPOS]; // [h][d][n] (transposed!)
__device__ float g_pm[HEADS * NPOS * NSPLIT];
__device__ float g_pl[HEADS * NPOS * NSPLIT];
__device__ __align__(16) float g_pacc[HEADS * NPOS * NSPLIT * DHEAD];
__device__ __align__(16) float g_o[HID * NPOS];                     // attention out fp32 [c][n]

// m16n8k16 bf16 MMA, fp32 accum, D==C in-place
__device__ __forceinline__ void mma16816(float* d, const uint32* a, uint32 b0, uint32 b1)
{
    asm volatile(
        "mma.sync.aligned.m16n8k16.row.col.f32.bf16.bf16.f32 "
        "{%0,%1,%2,%3},{%4,%5,%6,%7},{%8,%9},{%0,%1,%2,%3};"
        : "+f"(d[0]), "+f"(d[1]), "+f"(d[2]), "+f"(d[3])
        : "r"(a[0]), "r"(a[1]), "r"(a[2]), "r"(a[3]), "r"(b0), "r"(b1));
}

// m16n8k8 tf32 MMA, fp32 accum, D==C in-place
__device__ __forceinline__ void mma1688_tf32(float* d, const uint32* a, uint32 b0, uint32 b1)
{
    asm volatile(
        "mma.sync.aligned.m16n8k8.row.col.f32.tf32.tf32.f32 "
        "{%0,%1,%2,%3},{%4,%5,%6,%7},{%8,%9},{%0,%1,%2,%3};"
        : "+f"(d[0]), "+f"(d[1]), "+f"(d[2]), "+f"(d[3])
        : "r"(a[0]), "r"(a[1]), "r"(a[2]), "r"(a[3]), "r"(b0), "r"(b1));
}

__device__ __forceinline__ uint32 to_tf32(float f)
{
    uint32 r;
    asm("cvt.rna.tf32.f32 %0, %1;" : "=r"(r) : "f"(f));
    return r;
}

__device__ __forceinline__ uint32 pk2(float lo, float hi)
{
    __nv_bfloat162 t = __floats2bfloat162_rn(lo, hi);
    return *(uint32*)&t;
}

// ============================================================
// Kernel 1: QKV = w_qkv @ x (384x64 * 64x4096), fp32 math, bf16 stores.
// ============================================================
__global__ void qkv_kernel(const float* __restrict__ x, const float* __restrict__ w)
{
    int n = blockIdx.x * 128 + threadIdx.x;
    int og = blockIdx.y * 8;

    __shared__ float ws[8 * 64];
    for (int idx = threadIdx.x; idx < 8 * 64; idx += 128)
        ws[idx] = w[og * 64 + idx];
    __syncthreads();

    float acc[8];
#pragma unroll
    for (int k = 0; k < 8; k++) acc[k] = 0.f;

#pragma unroll 4
    for (int c = 0; c < CIN; c++) {
        float xv = x[c * NPOS + n];
#pragma unroll
        for (int k = 0; k < 8; k++) acc[k] += ws[k * 64 + c] * xv;
    }

    int seg = og >> 7;          // 0=q 1=k 2=v
    int oo = og & 127;
    int h = oo >> 5, d0 = oo & 31;

    if (seg < 2) {
        float scale = (seg == 0) ? 0.17677669529663687f : 1.f;  // 32^-0.5 on Q
        __nv_bfloat162 h0 = __floats2bfloat162_rn(acc[0] * scale, acc[1] * scale);
        __nv_bfloat162 h1 = __floats2bfloat162_rn(acc[2] * scale, acc[3] * scale);
        __nv_bfloat162 h2 = __floats2bfloat162_rn(acc[4] * scale, acc[5] * scale);
        __nv_bfloat162 h3 = __floats2bfloat162_rn(acc[6] * scale, acc[7] * scale);
        uint4 pk;
        pk.x = *(uint32*)&h0; pk.y = *(uint32*)&h1;
        pk.z = *(uint32*)&h2; pk.w = *(uint32*)&h3;
        __nv_bfloat16* base = (seg == 0 ? g_qtb : g_ktb) + (size_t)(h * NPOS + n) * DHEAD + d0;
        *(uint4*)base = pk;
    } else {
#pragma unroll
        for (int k = 0; k < 8; k++)
            g_vtb[(size_t)(h * DHEAD + d0 + k) * NPOS + n] = __float2bfloat16(acc[k]);
    }
}

// ============================================================
// Kernel 2: tensor-core flash attention (bf16 mma.sync, fp32 accum).
// (unchanged from the 98.5us round-9 version)
// ============================================================
__global__ void __launch_bounds__(256) flash_kernel()
{
    __shared__ __nv_bfloat16 sK[KT * 40];      // [64 keys][32 d], rows padded to 80B
    __shared__ __nv_bfloat16 sVt[DHEAD * 72];  // [32 d][64 keys], rows padded to 144B
    uint32* sKu = (uint32*)sK;
    uint32* sVu = (uint32*)sVt;

    int bx = blockIdx.x;
    int qblk = bx & 31, split = (bx >> 5) & 3, h = bx >> 7;
    int tid = threadIdx.x, w = tid >> 5, lane = tid & 31;
    int g = lane >> 2, tg = lane & 3;
    int q0 = qblk * 128 + w * 16;

    uint32 qa[2][4];
    {
        const uint32* Qb = (const uint32*)g_qtb + (size_t)(h * NPOS + q0) * 16;
#pragma unroll
        for (int ks = 0; ks < 2; ks++) {
            qa[ks][0] = Qb[g * 16 + tg + 8 * ks];
            qa[ks][1] = Qb[(g + 8) * 16 + tg + 8 * ks];
            qa[ks][2] = Qb[g * 16 + tg + 4 + 8 * ks];
            qa[ks][3] = Qb[(g + 8) * 16 + tg + 4 + 8 * ks];
        }
    }

    float o[4][4];
#pragma unroll
    for (int a = 0; a < 4; a++)
#pragma unroll
        for (int b = 0; b < 4; b++) o[a][b] = 0.f;
    float m0 = -1e30f, m1 = -1e30f, l0 = 0.f, l1 = 0.f;

    const uint32* Kg = (const uint32*)g_ktb + (size_t)(h * NPOS + split * CHUNK) * 16;
    const uint32* Vg = (const uint32*)g_vtb + (size_t)(h * DHEAD) * (NPOS / 2) + split * (CHUNK / 2);

    for (int tile = 0; tile < NTILES; tile++) {
        __syncthreads();
#pragma unroll
        for (int it = 0; it < 4; it++) {
            int idx = tid + it * 256;
            int row = idx >> 4, c = idx & 15;
            sKu[row * 20 + c] = Kg[(size_t)(tile * 64 + row) * 16 + c];
        }
#pragma unroll
        for (int it = 0; it < 4; it++) {
            int idx = tid + it * 256;
            int row = idx >> 5, c = idx & 31;
            sVu[row * 36 + c] = Vg[(size_t)row * (NPOS / 2) + tile * 32 + c];
        }
        __syncthreads();

#pragma unroll
        for (int kt = 0; kt < 4; kt++) {
            float s[2][4];
#pragma unroll
            for (int nt = 0; nt < 2; nt++)
#pragma unroll
                for (int c = 0; c < 4; c++) s[nt][c] = 0.f;

#pragma unroll
            for (int ks = 0; ks < 2; ks++) {
#pragma unroll
                for (int nt = 0; nt < 2; nt++) {
                    int krow = kt * 16 + nt * 8 + g;
                    uint32 b0 = sKu[krow * 20 + tg + 8 * ks];
                    uint32 b1 = sKu[krow * 20 + tg + 4 + 8 * ks];
                    mma16816(s[nt], qa[ks], b0, b1);
                }
            }

            float tm0 = fmaxf(fmaxf(s[0][0], s[0][1]), fmaxf(s[1][0], s[1][1]));
            float tm1 = fmaxf(fmaxf(s[0][2], s[0][3]), fmaxf(s[1][2], s[1][3]));
            tm0 = fmaxf(tm0, __shfl_xor_sync(0xffffffffu, tm0, 1));
            tm0 = fmaxf(tm0, __shfl_xor_sync(0xffffffffu, tm0, 2));
            tm1 = fmaxf(tm1, __shfl_xor_sync(0xffffffffu, tm1, 1));
            tm1 = fmaxf(tm1, __shfl_xor_sync(0xffffffffu, tm1, 2));
            float nm0 = fmaxf(m0, tm0), nm1 = fmaxf(m1, tm1);
            float c0 = exp2f((m0 - nm0) * L2E);
            float c1 = exp2f((m1 - nm1) * L2E);
            m0 = nm0; m1 = nm1;

            float p00 = exp2f((s[0][0] - nm0) * L2E);
            float p01 = exp2f((s[0][1] - nm0) * L2E);
            float p10 = exp2f((s[1][0] - nm0) * L2E);
            float p11 = exp2f((s[1][1] - nm0) * L2E);
            float p02 = exp2f((s[0][2] - nm1) * L2E);
            float p03 = exp2f((s[0][3] - nm1) * L2E);
            float p12 = exp2f((s[1][2] - nm1) * L2E);
            float p13 = exp2f((s[1][3] - nm1) * L2E);

            l0 = l0 * c0 + ((p00 + p01) + (p10 + p11));
            l1 = l1 * c1 + ((p02 + p03) + (p12 + p13));

#pragma unroll
            for (int nt = 0; nt < 4; nt++) {
                o[nt][0] *= c0; o[nt][1] *= c0;
                o[nt][2] *= c1; o[nt][3] *= c1;
            }

            uint32 pa[4];
            pa[0] = pk2(p00, p01);
            pa[1] = pk2(p02, p03);
            pa[2] = pk2(p10, p11);
            pa[3] = pk2(p12, p13);

#pragma unroll
            for (int nt = 0; nt < 4; nt++) {
                int vrow = nt * 8 + g;
                uint32 b0 = sVu[vrow * 36 + kt * 8 + tg];
                uint32 b1 = sVu[vrow * 36 + kt * 8 + tg + 4];
                mma16816(o[nt], pa, b0, b1);
            }
        }
    }

    l0 += __shfl_xor_sync(0xffffffffu, l0, 1);
    l0 += __shfl_xor_sync(0xffffffffu, l0, 2);
    l1 += __shfl_xor_sync(0xffffffffu, l1, 1);
    l1 += __shfl_xor_sync(0xffffffffu, l1, 2);

    int qg0 = h * NPOS + q0 + g;
    int qg1 = qg0 + 8;
    int pi0 = qg0 * NSPLIT + split;
    int pi1 = qg1 * NSPLIT + split;
    g_pm[pi0] = m0; g_pl[pi0] = l0;
    g_pm[pi1] = m1; g_pl[pi1] = l1;

    float2* P0 = (float2*)(g_pacc + (size_t)pi0 * 32);
    float2* P1 = (float2*)(g_pacc + (size_t)pi1 * 32);
#pragma unroll
    for (int nt = 0; nt < 4; nt++) {
        P0[nt * 4 + tg] = make_float2(o[nt][0], o[nt][1]);
        P1[nt * 4 + tg] = make_float2(o[nt][2], o[nt][3]);
    }
}

// ============================================================
// Kernel 3: combine NSPLIT partials, 4x wider than before.
// grid 512 x 128: blockIdx [0..127] -> query block, blockIdx>>7 -> d-quad.
// Thread handles 8 of the 32 d's; stores stay fully coalesced in n.
// ============================================================
__global__ void reduce_kernel()
{
    int quad = blockIdx.x >> 7;                       // 0..3 -> d = quad*8 .. +7
    int q = (blockIdx.x & 127) * 128 + threadIdx.x;   // h*4096+i
    int h = q >> 12;
    int i = q & 4095;
    int base = q * NSPLIT;

    float pm[NSPLIT], pl[NSPLIT];
#pragma unroll
    for (int s = 0; s < NSPLIT; s++) { pm[s] = g_pm[base + s]; pl[s] = g_pl[base + s]; }

    float M = fmaxf(fmaxf(pm[0], pm[1]), fmaxf(pm[2], pm[3]));

    float L = 0.f;
    float num[8];
#pragma unroll
    for (int d = 0; d < 8; d++) num[d] = 0.f;

#pragma unroll
    for (int s = 0; s < NSPLIT; s++) {
        float es = exp2f((pm[s] - M) * L2E);
        L += pl[s] * es;
        const float4* pa = (const float4*)(g_pacc + (size_t)(base + s) * 32 + quad * 8);
        float4 a0 = pa[0], a1 = pa[1];
        num[0] += a0.x * es; num[1] += a0.y * es;
        num[2] += a0.z * es; num[3] += a0.w * es;
        num[4] += a1.x * es; num[5] += a1.y * es;
        num[6] += a1.z * es; num[7] += a1.w * es;
    }
    float inv = 1.f / L;
#pragma unroll
    for (int d = 0; d < 8; d++)
        g_o[(size_t)(h * DHEAD + quad * 8 + d) * NPOS + i] = num[d] * inv;
}

// ============================================================
// Kernel 4: y = w_out @ O + b_out via tf32 MMA. No smem, no transposes:
// A = w_out[o][c] row-major (native), B = g_o[c][n] (native K x N col frag).
// 128 blocks x 8 warps; warp = 16 o x 16 n, k = 128 (16 MMA k-steps).
// ============================================================
__global__ void __launch_bounds__(256) outproj_kernel(
    const float* __restrict__ w, const float* __restrict__ b, float* __restrict__ y)
{
    int tid = threadIdx.x, wp = tid >> 5, lane = tid & 31;
    int g = lane >> 2, tg = lane & 3;
    int ow = wp & 3, nw = wp >> 2;                 // o-tile 0..3, n-half 0..1
    int o0 = ow * 16;
    int n0 = blockIdx.x * 32 + nw * 16;

    float c0[4] = {0.f, 0.f, 0.f, 0.f};
    float c1[4] = {0.f, 0.f, 0.f, 0.f};

    const float* wA0 = w + (size_t)(o0 + g) * HID;
    const float* wA1 = w + (size_t)(o0 + g + 8) * HID;

#pragma unroll
    for (int ks = 0; ks < 16; ks++) {
        int k0 = ks * 8;
        uint32 a[4];
        a[0] = to_tf32(wA0[k0 + tg]);
        a[1] = to_tf32(wA1[k0 + tg]);
        a[2] = to_tf32(wA0[k0 + tg + 4]);
        a[3] = to_tf32(wA1[k0 + tg + 4]);

        const float* B0 = g_o + (size_t)(k0 + tg) * NPOS + n0 + g;
        const float* B1 = g_o + (size_t)(k0 + tg + 4) * NPOS + n0 + g;
        uint32 b00 = to_tf32(B0[0]);
        uint32 b01 = to_tf32(B1[0]);
        uint32 b10 = to_tf32(B0[8]);
        uint32 b11 = to_tf32(B1[8]);
        mma1688_tf32(c0, a, b00, b01);
        mma1688_tf32(c1, a, b10, b11);
    }

    float bb0 = b[o0 + g];
    float bb1 = b[o0 + g + 8];
    float2* Y0 = (float2*)(y + (size_t)(o0 + g) * NPOS + n0 + 2 * tg);
    float2* Y1 = (float2*)(y + (size_t)(o0 + g + 8) * NPOS + n0 + 2 * tg);
    Y0[0] = make_float2(c0[0] + bb0, c0[1] + bb0);
    Y1[0] = make_float2(c0[2] + bb1, c0[3] + bb1);
    Y0[4] = make_float2(c1[0] + bb0, c1[1] + bb0);   // +8 floats = 4 float2
    Y1[4] = make_float2(c1[2] + bb1, c1[3] + bb1);
}

// ============================================================
extern "C" void kernel_launch(void* const* d_in, const int* in_sizes, int n_in,
                              void* d_out, int out_size)
{
    const float* x     = (const float*)d_in[0];
    const float* w_qkv = (const float*)d_in[1];
    const float* w_out = (const float*)d_in[2];
    const float* b_out = (const float*)d_in[3];
    float* y = (float*)d_out;

    qkv_kernel<<<dim3(NPOS / 128, 48), 128>>>(x, w_qkv);
    flash_kernel<<<512, 256>>>();
    reduce_kernel<<<512, 128>>>();
    outproj_kernel<<<128, 256>>>(w_out, b_out, y);
}

// round 13
// speedup vs baseline: 1.2490x; 1.1017x over previous
#include <cuda_runtime.h>
#include <cuda_bf16.h>

#define HEADS 4
#define DHEAD 32
#define HID 128
#define CIN 64
#define NPOS 4096
#define NSPLIT 4
#define CHUNK (NPOS / NSPLIT) /* 1024 */
#define KT 64                 /* keys per smem tile */
#define NTILES (CHUNK / KT)   /* 16 */
#define L2E 1.4426950408889634f

typedef unsigned int uint32;

// ---- device scratch ----
__device__ __align__(16) __nv_bfloat16 g_qtb[HEADS * NPOS * DHEAD]; // [h][n][d], scaled
__device__ __align__(16) __nv_bfloat16 g_ktb[HEADS * NPOS * DHEAD]; // [h][n][d]
__device__ __align__(16) __nv_bfloat16 g_vtb[HEADS * DHEAD * NPOS]; // [h][d][n] (transposed!)
__device__ float g_pm[HEADS * NPOS * NSPLIT];
__device__ float g_pl[HEADS * NPOS * NSPLIT];
__device__ __align__(16) float g_pacc[HEADS * NPOS * NSPLIT * DHEAD];
__device__ __align__(16) float g_o[HID * NPOS];                     // attention out fp32 [c][n]

// m16n8k16 bf16 MMA, fp32 accum, D==C in-place
__device__ __forceinline__ void mma16816(float* d, const uint32* a, uint32 b0, uint32 b1)
{
    asm volatile(
        "mma.sync.aligned.m16n8k16.row.col.f32.bf16.bf16.f32 "
        "{%0,%1,%2,%3},{%4,%5,%6,%7},{%8,%9},{%0,%1,%2,%3};"
        : "+f"(d[0]), "+f"(d[1]), "+f"(d[2]), "+f"(d[3])
        : "r"(a[0]), "r"(a[1]), "r"(a[2]), "r"(a[3]), "r"(b0), "r"(b1));
}

// m16n8k8 tf32 MMA, fp32 accum, D==C in-place
__device__ __forceinline__ void mma1688_tf32(float* d, const uint32* a, uint32 b0, uint32 b1)
{
    asm volatile(
        "mma.sync.aligned.m16n8k8.row.col.f32.tf32.tf32.f32 "
        "{%0,%1,%2,%3},{%4,%5,%6,%7},{%8,%9},{%0,%1,%2,%3};"
        : "+f"(d[0]), "+f"(d[1]), "+f"(d[2]), "+f"(d[3])
        : "r"(a[0]), "r"(a[1]), "r"(a[2]), "r"(a[3]), "r"(b0), "r"(b1));
}

__device__ __forceinline__ uint32 to_tf32(float f)
{
    uint32 r;
    asm("cvt.rna.tf32.f32 %0, %1;" : "=r"(r) : "f"(f));
    return r;
}

__device__ __forceinline__ float ex2(float x)   // single MUFU.EX2
{
    float y;
    asm("ex2.approx.f32 %0, %1;" : "=f"(y) : "f"(x));
    return y;
}

__device__ __forceinline__ uint32 pk2(float lo, float hi)
{
    __nv_bfloat162 t = __floats2bfloat162_rn(lo, hi);
    return *(uint32*)&t;
}

// ============================================================
// Kernel 1: QKV = w_qkv @ x (384x64 * 64x4096), fp32 math, bf16 stores.
// ============================================================
__global__ void qkv_kernel(const float* __restrict__ x, const float* __restrict__ w)
{
    int n = blockIdx.x * 128 + threadIdx.x;
    int og = blockIdx.y * 8;

    __shared__ float ws[8 * 64];
    for (int idx = threadIdx.x; idx < 8 * 64; idx += 128)
        ws[idx] = w[og * 64 + idx];
    __syncthreads();

    float acc[8];
#pragma unroll
    for (int k = 0; k < 8; k++) acc[k] = 0.f;

#pragma unroll 4
    for (int c = 0; c < CIN; c++) {
        float xv = x[c * NPOS + n];
#pragma unroll
        for (int k = 0; k < 8; k++) acc[k] += ws[k * 64 + c] * xv;
    }

    int seg = og >> 7;          // 0=q 1=k 2=v
    int oo = og & 127;
    int h = oo >> 5, d0 = oo & 31;

    if (seg < 2) {
        float scale = (seg == 0) ? 0.17677669529663687f : 1.f;  // 32^-0.5 on Q
        __nv_bfloat162 h0 = __floats2bfloat162_rn(acc[0] * scale, acc[1] * scale);
        __nv_bfloat162 h1 = __floats2bfloat162_rn(acc[2] * scale, acc[3] * scale);
        __nv_bfloat162 h2 = __floats2bfloat162_rn(acc[4] * scale, acc[5] * scale);
        __nv_bfloat162 h3 = __floats2bfloat162_rn(acc[6] * scale, acc[7] * scale);
        uint4 pk;
        pk.x = *(uint32*)&h0; pk.y = *(uint32*)&h1;
        pk.z = *(uint32*)&h2; pk.w = *(uint32*)&h3;
        __nv_bfloat16* base = (seg == 0 ? g_qtb : g_ktb) + (size_t)(h * NPOS + n) * DHEAD + d0;
        *(uint4*)base = pk;
    } else {
#pragma unroll
        for (int k = 0; k < 8; k++)
            g_vtb[(size_t)(h * DHEAD + d0 + k) * NPOS + n] = __float2bfloat16(acc[k]);
    }
}

// ============================================================
// Kernel 2: tensor-core flash attention, batched softmax per 64-key tile.
// grid 512: bx = h(4) x split(4) x qblk(32). Block 256 = 8 warps,
// each warp owns 16 queries. Per tile: 16 S-MMAs, ONE softmax pass, 16 PV-MMAs.
// ============================================================
__global__ void __launch_bounds__(256) flash_kernel()
{
    __shared__ __nv_bfloat16 sK[KT * 40];      // [64 keys][32 d], rows padded to 80B
    __shared__ __nv_bfloat16 sVt[DHEAD * 72];  // [32 d][64 keys], rows padded to 144B
    uint32* sKu = (uint32*)sK;
    uint32* sVu = (uint32*)sVt;

    int bx = blockIdx.x;
    int qblk = bx & 31, split = (bx >> 5) & 3, h = bx >> 7;
    int tid = threadIdx.x, w = tid >> 5, lane = tid & 31;
    int g = lane >> 2, tg = lane & 3;
    int q0 = qblk * 128 + w * 16;

    uint32 qa[2][4];
    {
        const uint32* Qb = (const uint32*)g_qtb + (size_t)(h * NPOS + q0) * 16;
#pragma unroll
        for (int ks = 0; ks < 2; ks++) {
            qa[ks][0] = Qb[g * 16 + tg + 8 * ks];
            qa[ks][1] = Qb[(g + 8) * 16 + tg + 8 * ks];
            qa[ks][2] = Qb[g * 16 + tg + 4 + 8 * ks];
            qa[ks][3] = Qb[(g + 8) * 16 + tg + 4 + 8 * ks];
        }
    }

    float o[4][4];
#pragma unroll
    for (int a = 0; a < 4; a++)
#pragma unroll
        for (int b = 0; b < 4; b++) o[a][b] = 0.f;
    float m0 = -1e30f, m1 = -1e30f, l0 = 0.f, l1 = 0.f;

    const uint32* Kg = (const uint32*)g_ktb + (size_t)(h * NPOS + split * CHUNK) * 16;
    const uint32* Vg = (const uint32*)g_vtb + (size_t)(h * DHEAD) * (NPOS / 2) + split * (CHUNK / 2);

    for (int tile = 0; tile < NTILES; tile++) {
        __syncthreads();
#pragma unroll
        for (int it = 0; it < 4; it++) {
            int idx = tid + it * 256;
            int row = idx >> 4, c = idx & 15;
            sKu[row * 20 + c] = Kg[(size_t)(tile * 64 + row) * 16 + c];
        }
#pragma unroll
        for (int it = 0; it < 4; it++) {
            int idx = tid + it * 256;
            int row = idx >> 5, c = idx & 31;
            sVu[row * 36 + c] = Vg[(size_t)row * (NPOS / 2) + tile * 32 + c];
        }
        __syncthreads();

        // ---- Phase 1: all 64 keys' S values (16 MMAs) ----
        float sS[4][2][4];
#pragma unroll
        for (int kt = 0; kt < 4; kt++) {
#pragma unroll
            for (int nt = 0; nt < 2; nt++)
#pragma unroll
                for (int c = 0; c < 4; c++) sS[kt][nt][c] = 0.f;
#pragma unroll
            for (int ks = 0; ks < 2; ks++) {
#pragma unroll
                for (int nt = 0; nt < 2; nt++) {
                    int krow = kt * 16 + nt * 8 + g;
                    uint32 b0 = sKu[krow * 20 + tg + 8 * ks];
                    uint32 b1 = sKu[krow * 20 + tg + 4 + 8 * ks];
                    mma16816(sS[kt][nt], qa[ks], b0, b1);
                }
            }
        }

        // ---- Phase 2: ONE softmax bookkeeping pass for all 64 keys ----
        float tm0 = -1e30f, tm1 = -1e30f;
#pragma unroll
        for (int kt = 0; kt < 4; kt++) {
#pragma unroll
            for (int nt = 0; nt < 2; nt++) {
                tm0 = fmaxf(tm0, fmaxf(sS[kt][nt][0], sS[kt][nt][1]));
                tm1 = fmaxf(tm1, fmaxf(sS[kt][nt][2], sS[kt][nt][3]));
            }
        }
        tm0 = fmaxf(tm0, __shfl_xor_sync(0xffffffffu, tm0, 1));
        tm0 = fmaxf(tm0, __shfl_xor_sync(0xffffffffu, tm0, 2));
        tm1 = fmaxf(tm1, __shfl_xor_sync(0xffffffffu, tm1, 1));
        tm1 = fmaxf(tm1, __shfl_xor_sync(0xffffffffu, tm1, 2));
        float nm0 = fmaxf(m0, tm0), nm1 = fmaxf(m1, tm1);
        float c0 = ex2((m0 - nm0) * L2E);
        float c1 = ex2((m1 - nm1) * L2E);
        m0 = nm0; m1 = nm1;
        l0 *= c0; l1 *= c1;
#pragma unroll
        for (int nt = 0; nt < 4; nt++) {
            o[nt][0] *= c0; o[nt][1] *= c0;
            o[nt][2] *= c1; o[nt][3] *= c1;
        }

        // ---- Phase 3: exp + PV MMAs ----
#pragma unroll
        for (int kt = 0; kt < 4; kt++) {
            float p00 = ex2((sS[kt][0][0] - nm0) * L2E);
            float p01 = ex2((sS[kt][0][1] - nm0) * L2E);
            float p10 = ex2((sS[kt][1][0] - nm0) * L2E);
            float p11 = ex2((sS[kt][1][1] - nm0) * L2E);
            float p02 = ex2((sS[kt][0][2] - nm1) * L2E);
            float p03 = ex2((sS[kt][0][3] - nm1) * L2E);
            float p12 = ex2((sS[kt][1][2] - nm1) * L2E);
            float p13 = ex2((sS[kt][1][3] - nm1) * L2E);

            l0 += (p00 + p01) + (p10 + p11);
            l1 += (p02 + p03) + (p12 + p13);

            uint32 pa[4];
            pa[0] = pk2(p00, p01);
            pa[1] = pk2(p02, p03);
            pa[2] = pk2(p10, p11);
            pa[3] = pk2(p12, p13);

#pragma unroll
            for (int nt = 0; nt < 4; nt++) {
                int vrow = nt * 8 + g;
                uint32 b0 = sVu[vrow * 36 + kt * 8 + tg];
                uint32 b1 = sVu[vrow * 36 + kt * 8 + tg + 4];
                mma16816(o[nt], pa, b0, b1);
            }
        }
    }

    l0 += __shfl_xor_sync(0xffffffffu, l0, 1);
    l0 += __shfl_xor_sync(0xffffffffu, l0, 2);
    l1 += __shfl_xor_sync(0xffffffffu, l1, 1);
    l1 += __shfl_xor_sync(0xffffffffu, l1, 2);

    int qg0 = h * NPOS + q0 + g;
    int qg1 = qg0 + 8;
    int pi0 = qg0 * NSPLIT + split;
    int pi1 = qg1 * NSPLIT + split;
    g_pm[pi0] = m0; g_pl[pi0] = l0;
    g_pm[pi1] = m1; g_pl[pi1] = l1;

    float2* P0 = (float2*)(g_pacc + (size_t)pi0 * 32);
    float2* P1 = (float2*)(g_pacc + (size_t)pi1 * 32);
#pragma unroll
    for (int nt = 0; nt < 4; nt++) {
        P0[nt * 4 + tg] = make_float2(o[nt][0], o[nt][1]);
        P1[nt * 4 + tg] = make_float2(o[nt][2], o[nt][3]);
    }
}

// ============================================================
// Kernel 3: combine NSPLIT partials (4x wide).
// ============================================================
__global__ void reduce_kernel()
{
    int quad = blockIdx.x >> 7;                       // 0..3 -> d = quad*8 .. +7
    int q = (blockIdx.x & 127) * 128 + threadIdx.x;   // h*4096+i
    int h = q >> 12;
    int i = q & 4095;
    int base = q * NSPLIT;

    float pm[NSPLIT], pl[NSPLIT];
#pragma unroll
    for (int s = 0; s < NSPLIT; s++) { pm[s] = g_pm[base + s]; pl[s] = g_pl[base + s]; }

    float M = fmaxf(fmaxf(pm[0], pm[1]), fmaxf(pm[2], pm[3]));

    float L = 0.f;
    float num[8];
#pragma unroll
    for (int d = 0; d < 8; d++) num[d] = 0.f;

#pragma unroll
    for (int s = 0; s < NSPLIT; s++) {
        float es = ex2((pm[s] - M) * L2E);
        L += pl[s] * es;
        const float4* pa = (const float4*)(g_pacc + (size_t)(base + s) * 32 + quad * 8);
        float4 a0 = pa[0], a1 = pa[1];
        num[0] += a0.x * es; num[1] += a0.y * es;
        num[2] += a0.z * es; num[3] += a0.w * es;
        num[4] += a1.x * es; num[5] += a1.y * es;
        num[6] += a1.z * es; num[7] += a1.w * es;
    }
    float inv = 1.f / L;
#pragma unroll
    for (int d = 0; d < 8; d++)
        g_o[(size_t)(h * DHEAD + quad * 8 + d) * NPOS + i] = num[d] * inv;
}

// ============================================================
// Kernel 4: y = w_out @ O + b_out via tf32 MMA, 2048 warps.
// 256 blocks x 8 warps; warp = 16 o x 8 n, k = 128 (16 MMA k-steps).
// A = w_out[o][c] row-major, B = g_o[c][n] native col fragment; no smem.
// ============================================================
__global__ void __launch_bounds__(256) outproj_kernel(
    const float* __restrict__ w, const float* __restrict__ b, float* __restrict__ y)
{
    int tid = threadIdx.x, wp = tid >> 5, lane = tid & 31;
    int g = lane >> 2, tg = lane & 3;
    int ow = wp & 3, nw = wp >> 2;                 // o-tile 0..3, n-sub 0..1
    int o0 = ow * 16;
    int n0 = blockIdx.x * 16 + nw * 8;

    float c[4] = {0.f, 0.f, 0.f, 0.f};

    const float* wA0 = w + (size_t)(o0 + g) * HID;
    const float* wA1 = w + (size_t)(o0 + g + 8) * HID;

#pragma unroll
    for (int ks = 0; ks < 16; ks++) {
        int k0 = ks * 8;
        uint32 a[4];
        a[0] = to_tf32(wA0[k0 + tg]);
        a[1] = to_tf32(wA1[k0 + tg]);
        a[2] = to_tf32(wA0[k0 + tg + 4]);
        a[3] = to_tf32(wA1[k0 + tg + 4]);

        uint32 b0 = to_tf32(g_o[(size_t)(k0 + tg) * NPOS + n0 + g]);
        uint32 b1 = to_tf32(g_o[(size_t)(k0 + tg + 4) * NPOS + n0 + g]);
        mma1688_tf32(c, a, b0, b1);
    }

    float bb0 = b[o0 + g];
    float bb1 = b[o0 + g + 8];
    *(float2*)(y + (size_t)(o0 + g) * NPOS + n0 + 2 * tg)     = make_float2(c[0] + bb0, c[1] + bb0);
    *(float2*)(y + (size_t)(o0 + g + 8) * NPOS + n0 + 2 * tg) = make_float2(c[2] + bb1, c[3] + bb1);
}

// ============================================================
extern "C" void kernel_launch(void* const* d_in, const int* in_sizes, int n_in,
                              void* d_out, int out_size)
{
    const float* x     = (const float*)d_in[0];
    const float* w_qkv = (const float*)d_in[1];
    const float* w_out = (const float*)d_in[2];
    const float* b_out = (const float*)d_in[3];
    float* y = (float*)d_out;

    qkv_kernel<<<dim3(NPOS / 128, 48), 128>>>(x, w_qkv);
    flash_kernel<<<512, 256>>>();
    reduce_kernel<<<512, 128>>>();
    outproj_kernel<<<256, 256>>>(w_out, b_out, y);
}

// round 14
// speedup vs baseline: 1.3764x; 1.1020x over previous
#include <cuda_runtime.h>
#include <cuda_bf16.h>

#define HEADS 4
#define DHEAD 32
#define HID 128
#define CIN 64
#define NPOS 4096
#define NSPLIT 4
#define CHUNK (NPOS / NSPLIT) /* 1024 */
#define KT 64                 /* keys per smem tile */
#define NTILES (CHUNK / KT)   /* 16 */
#define L2E 1.4426950408889634f
#define OPAD 40               /* sO row pitch (words); 40 % 32 == 8 -> conflict-free quads */

typedef unsigned int uint32;

// ---- device scratch ----
__device__ __align__(16) __nv_bfloat16 g_qtb[HEADS * NPOS * DHEAD]; // [h][n][d], scaled
__device__ __align__(16) __nv_bfloat16 g_ktb[HEADS * NPOS * DHEAD]; // [h][n][d]
__device__ __align__(16) __nv_bfloat16 g_vtb[HEADS * DHEAD * NPOS]; // [h][d][n]
__device__ float g_pm[HEADS * NPOS * NSPLIT];
__device__ float g_pl[HEADS * NPOS * NSPLIT];
__device__ __align__(16) float g_pacc[HEADS * NPOS * NSPLIT * DHEAD];

// m16n8k16 bf16 MMA, fp32 accum, D==C in-place
__device__ __forceinline__ void mma16816(float* d, const uint32* a, uint32 b0, uint32 b1)
{
    asm volatile(
        "mma.sync.aligned.m16n8k16.row.col.f32.bf16.bf16.f32 "
        "{%0,%1,%2,%3},{%4,%5,%6,%7},{%8,%9},{%0,%1,%2,%3};"
        : "+f"(d[0]), "+f"(d[1]), "+f"(d[2]), "+f"(d[3])
        : "r"(a[0]), "r"(a[1]), "r"(a[2]), "r"(a[3]), "r"(b0), "r"(b1));
}

// m16n8k8 tf32 MMA, fp32 accum, D==C in-place
__device__ __forceinline__ void mma1688_tf32(float* d, const uint32* a, uint32 b0, uint32 b1)
{
    asm volatile(
        "mma.sync.aligned.m16n8k8.row.col.f32.tf32.tf32.f32 "
        "{%0,%1,%2,%3},{%4,%5,%6,%7},{%8,%9},{%0,%1,%2,%3};"
        : "+f"(d[0]), "+f"(d[1]), "+f"(d[2]), "+f"(d[3])
        : "r"(a[0]), "r"(a[1]), "r"(a[2]), "r"(a[3]), "r"(b0), "r"(b1));
}

__device__ __forceinline__ uint32 to_tf32(float f)
{
    uint32 r;
    asm("cvt.rna.tf32.f32 %0, %1;" : "=r"(r) : "f"(f));
    return r;
}

__device__ __forceinline__ float ex2(float x)
{
    float y;
    asm("ex2.approx.f32 %0, %1;" : "=f"(y) : "f"(x));
    return y;
}

__device__ __forceinline__ uint32 pk2(float lo, float hi)
{
    __nv_bfloat162 t = __floats2bfloat162_rn(lo, hi);
    return *(uint32*)&t;
}

// ============================================================
// Kernel 1: QKV = w_qkv @ x (384x64 * 64x4096), fp32 math, bf16 stores.
// ============================================================
__global__ void qkv_kernel(const float* __restrict__ x, const float* __restrict__ w)
{
    int n = blockIdx.x * 128 + threadIdx.x;
    int og = blockIdx.y * 8;

    __shared__ float ws[8 * 64];
    for (int idx = threadIdx.x; idx < 8 * 64; idx += 128)
        ws[idx] = w[og * 64 + idx];
    __syncthreads();

    float acc[8];
#pragma unroll
    for (int k = 0; k < 8; k++) acc[k] = 0.f;

#pragma unroll 4
    for (int c = 0; c < CIN; c++) {
        float xv = x[c * NPOS + n];
#pragma unroll
        for (int k = 0; k < 8; k++) acc[k] += ws[k * 64 + c] * xv;
    }

    int seg = og >> 7;          // 0=q 1=k 2=v
    int oo = og & 127;
    int h = oo >> 5, d0 = oo & 31;

    if (seg < 2) {
        float scale = (seg == 0) ? 0.17677669529663687f : 1.f;
        __nv_bfloat162 h0 = __floats2bfloat162_rn(acc[0] * scale, acc[1] * scale);
        __nv_bfloat162 h1 = __floats2bfloat162_rn(acc[2] * scale, acc[3] * scale);
        __nv_bfloat162 h2 = __floats2bfloat162_rn(acc[4] * scale, acc[5] * scale);
        __nv_bfloat162 h3 = __floats2bfloat162_rn(acc[6] * scale, acc[7] * scale);
        uint4 pk;
        pk.x = *(uint32*)&h0; pk.y = *(uint32*)&h1;
        pk.z = *(uint32*)&h2; pk.w = *(uint32*)&h3;
        __nv_bfloat16* base = (seg == 0 ? g_qtb : g_ktb) + (size_t)(h * NPOS + n) * DHEAD + d0;
        *(uint4*)base = pk;
    } else {
#pragma unroll
        for (int k = 0; k < 8; k++)
            g_vtb[(size_t)(h * DHEAD + d0 + k) * NPOS + n] = __float2bfloat16(acc[k]);
    }
}

// ============================================================
// Kernel 2: tensor-core flash attention, batched softmax, K/V prefetch.
// ============================================================
__global__ void __launch_bounds__(256) flash_kernel()
{
    __shared__ __nv_bfloat16 sK[KT * 40];      // [64 keys][32 d], rows padded to 80B
    __shared__ __nv_bfloat16 sVt[DHEAD * 72];  // [32 d][64 keys], rows padded to 144B
    uint32* sKu = (uint32*)sK;
    uint32* sVu = (uint32*)sVt;

    int bx = blockIdx.x;
    int qblk = bx & 31, split = (bx >> 5) & 3, h = bx >> 7;
    int tid = threadIdx.x, w = tid >> 5, lane = tid & 31;
    int g = lane >> 2, tg = lane & 3;
    int q0 = qblk * 128 + w * 16;

    uint32 qa[2][4];
    {
        const uint32* Qb = (const uint32*)g_qtb + (size_t)(h * NPOS + q0) * 16;
#pragma unroll
        for (int ks = 0; ks < 2; ks++) {
            qa[ks][0] = Qb[g * 16 + tg + 8 * ks];
            qa[ks][1] = Qb[(g + 8) * 16 + tg + 8 * ks];
            qa[ks][2] = Qb[g * 16 + tg + 4 + 8 * ks];
            qa[ks][3] = Qb[(g + 8) * 16 + tg + 4 + 8 * ks];
        }
    }

    float o[4][4];
#pragma unroll
    for (int a = 0; a < 4; a++)
#pragma unroll
        for (int b = 0; b < 4; b++) o[a][b] = 0.f;
    float m0 = -1e30f, m1 = -1e30f, l0 = 0.f, l1 = 0.f;

    const uint32* Kg = (const uint32*)g_ktb + (size_t)(h * NPOS + split * CHUNK) * 16;
    const uint32* Vg = (const uint32*)g_vtb + (size_t)(h * DHEAD) * (NPOS / 2) + split * (CHUNK / 2);

    // K-staging coords: idx = tid + it*256 -> row=idx>>4, col=idx&15
    int krow_st[4], kcol_st[4], vrow_st[4], vcol_st[4];
#pragma unroll
    for (int it = 0; it < 4; it++) {
        int idx = tid + it * 256;
        krow_st[it] = idx >> 4; kcol_st[it] = idx & 15;
        vrow_st[it] = idx >> 5; vcol_st[it] = idx & 31;
    }

    // prefetch tile 0
    uint32 pkf[4], pvf[4];
#pragma unroll
    for (int it = 0; it < 4; it++) {
        pkf[it] = Kg[(size_t)krow_st[it] * 16 + kcol_st[it]];
        pvf[it] = Vg[(size_t)vrow_st[it] * (NPOS / 2) + vcol_st[it]];
    }

    for (int tile = 0; tile < NTILES; tile++) {
        __syncthreads();   // consumers of previous tile done
#pragma unroll
        for (int it = 0; it < 4; it++) {
            sKu[krow_st[it] * 20 + kcol_st[it]] = pkf[it];
            sVu[vrow_st[it] * 36 + vcol_st[it]] = pvf[it];
        }
        __syncthreads();

        // prefetch next tile (overlaps with compute below)
        if (tile + 1 < NTILES) {
#pragma unroll
            for (int it = 0; it < 4; it++) {
                pkf[it] = Kg[(size_t)((tile + 1) * 64 + krow_st[it]) * 16 + kcol_st[it]];
                pvf[it] = Vg[(size_t)vrow_st[it] * (NPOS / 2) + (tile + 1) * 32 + vcol_st[it]];
            }
        }

        // ---- Phase 1: all 64 keys' S values (16 MMAs) ----
        float sS[4][2][4];
#pragma unroll
        for (int kt = 0; kt < 4; kt++) {
#pragma unroll
            for (int nt = 0; nt < 2; nt++)
#pragma unroll
                for (int c = 0; c < 4; c++) sS[kt][nt][c] = 0.f;
#pragma unroll
            for (int ks = 0; ks < 2; ks++) {
#pragma unroll
                for (int nt = 0; nt < 2; nt++) {
                    int krow = kt * 16 + nt * 8 + g;
                    uint32 b0 = sKu[krow * 20 + tg + 8 * ks];
                    uint32 b1 = sKu[krow * 20 + tg + 4 + 8 * ks];
                    mma16816(sS[kt][nt], qa[ks], b0, b1);
                }
            }
        }

        // ---- Phase 2: one softmax bookkeeping pass ----
        float tm0 = -1e30f, tm1 = -1e30f;
#pragma unroll
        for (int kt = 0; kt < 4; kt++) {
#pragma unroll
            for (int nt = 0; nt < 2; nt++) {
                tm0 = fmaxf(tm0, fmaxf(sS[kt][nt][0], sS[kt][nt][1]));
                tm1 = fmaxf(tm1, fmaxf(sS[kt][nt][2], sS[kt][nt][3]));
            }
        }
        tm0 = fmaxf(tm0, __shfl_xor_sync(0xffffffffu, tm0, 1));
        tm0 = fmaxf(tm0, __shfl_xor_sync(0xffffffffu, tm0, 2));
        tm1 = fmaxf(tm1, __shfl_xor_sync(0xffffffffu, tm1, 1));
        tm1 = fmaxf(tm1, __shfl_xor_sync(0xffffffffu, tm1, 2));
        float nm0 = fmaxf(m0, tm0), nm1 = fmaxf(m1, tm1);
        float c0 = ex2((m0 - nm0) * L2E);
        float c1 = ex2((m1 - nm1) * L2E);
        m0 = nm0; m1 = nm1;
        l0 *= c0; l1 *= c1;
#pragma unroll
        for (int nt = 0; nt < 4; nt++) {
            o[nt][0] *= c0; o[nt][1] *= c0;
            o[nt][2] *= c1; o[nt][3] *= c1;
        }

        // ---- Phase 3: exp + PV MMAs ----
#pragma unroll
        for (int kt = 0; kt < 4; kt++) {
            float p00 = ex2((sS[kt][0][0] - nm0) * L2E);
            float p01 = ex2((sS[kt][0][1] - nm0) * L2E);
            float p10 = ex2((sS[kt][1][0] - nm0) * L2E);
            float p11 = ex2((sS[kt][1][1] - nm0) * L2E);
            float p02 = ex2((sS[kt][0][2] - nm1) * L2E);
            float p03 = ex2((sS[kt][0][3] - nm1) * L2E);
            float p12 = ex2((sS[kt][1][2] - nm1) * L2E);
            float p13 = ex2((sS[kt][1][3] - nm1) * L2E);

            l0 += (p00 + p01) + (p10 + p11);
            l1 += (p02 + p03) + (p12 + p13);

            uint32 pa[4];
            pa[0] = pk2(p00, p01);
            pa[1] = pk2(p02, p03);
            pa[2] = pk2(p10, p11);
            pa[3] = pk2(p12, p13);

#pragma unroll
            for (int nt = 0; nt < 4; nt++) {
                int vrow = nt * 8 + g;
                uint32 b0 = sVu[vrow * 36 + kt * 8 + tg];
                uint32 b1 = sVu[vrow * 36 + kt * 8 + tg + 4];
                mma16816(o[nt], pa, b0, b1);
            }
        }
    }

    l0 += __shfl_xor_sync(0xffffffffu, l0, 1);
    l0 += __shfl_xor_sync(0xffffffffu, l0, 2);
    l1 += __shfl_xor_sync(0xffffffffu, l1, 1);
    l1 += __shfl_xor_sync(0xffffffffu, l1, 2);

    int qg0 = h * NPOS + q0 + g;
    int qg1 = qg0 + 8;
    int pi0 = qg0 * NSPLIT + split;
    int pi1 = qg1 * NSPLIT + split;
    g_pm[pi0] = m0; g_pl[pi0] = l0;
    g_pm[pi1] = m1; g_pl[pi1] = l1;

    float2* P0 = (float2*)(g_pacc + (size_t)pi0 * 32);
    float2* P1 = (float2*)(g_pacc + (size_t)pi1 * 32);
#pragma unroll
    for (int nt = 0; nt < 4; nt++) {
        P0[nt * 4 + tg] = make_float2(o[nt][0], o[nt][1]);
        P1[nt * 4 + tg] = make_float2(o[nt][2], o[nt][3]);
    }
}

// ============================================================
// Kernel 3 (FUSED reduce + outproj): block owns 16 n-positions.
// Phase A: reduce split partials -> sO[128c][16n] in smem (pitch 40).
// Phase B: y[o][n] = w_out[o][:] @ sO + b via tf32 MMA (B from smem).
// ============================================================
__global__ void __launch_bounds__(256) fused_out_kernel(
    const float* __restrict__ w, const float* __restrict__ b, float* __restrict__ y)
{
    __shared__ float sO[HID * OPAD];   // 20.5 KB
    int tid = threadIdx.x;
    int n0 = blockIdx.x * 16;

    // ---- Phase A: 64 (h,i) pairs, 4 threads each (8 d's per thread) ----
    {
        int pair = tid >> 2;            // 0..63
        int hh = pair >> 4;             // head
        int il = pair & 15;             // local n
        int dq = (tid & 3) * 8;         // d offset
        int i = n0 + il;
        int base = (hh * NPOS + i) * NSPLIT;

        float pm[NSPLIT], pl[NSPLIT];
#pragma unroll
        for (int s = 0; s < NSPLIT; s++) { pm[s] = g_pm[base + s]; pl[s] = g_pl[base + s]; }
        float M = fmaxf(fmaxf(pm[0], pm[1]), fmaxf(pm[2], pm[3]));

        float L = 0.f;
        float num[8];
#pragma unroll
        for (int d = 0; d < 8; d++) num[d] = 0.f;

#pragma unroll
        for (int s = 0; s < NSPLIT; s++) {
            float es = ex2((pm[s] - M) * L2E);
            L += pl[s] * es;
            const float4* pa = (const float4*)(g_pacc + (size_t)(base + s) * 32 + dq);
            float4 a0 = pa[0], a1 = pa[1];
            num[0] += a0.x * es; num[1] += a0.y * es;
            num[2] += a0.z * es; num[3] += a0.w * es;
            num[4] += a1.x * es; num[5] += a1.y * es;
            num[6] += a1.z * es; num[7] += a1.w * es;
        }
        float inv = 1.f / L;
#pragma unroll
        for (int d = 0; d < 8; d++)
            sO[(hh * DHEAD + dq + d) * OPAD + il] = num[d] * inv;
    }
    __syncthreads();

    // ---- Phase B: tf32 MMA, 8 warps = 4 o-tiles x 2 n-subs ----
    int wp = tid >> 5, lane = tid & 31;
    int g = lane >> 2, tg = lane & 3;
    int ow = wp & 3, nw = wp >> 2;
    int o0 = ow * 16;
    int nl0 = nw * 8;

    float c[4] = {0.f, 0.f, 0.f, 0.f};
    const float* wA0 = w + (size_t)(o0 + g) * HID;
    const float* wA1 = w + (size_t)(o0 + g + 8) * HID;

#pragma unroll
    for (int ks = 0; ks < 16; ks++) {
        int k0 = ks * 8;
        uint32 a[4];
        a[0] = to_tf32(wA0[k0 + tg]);
        a[1] = to_tf32(wA1[k0 + tg]);
        a[2] = to_tf32(wA0[k0 + tg + 4]);
        a[3] = to_tf32(wA1[k0 + tg + 4]);

        uint32 b0 = to_tf32(sO[(k0 + tg) * OPAD + nl0 + g]);
        uint32 b1 = to_tf32(sO[(k0 + tg + 4) * OPAD + nl0 + g]);
        mma1688_tf32(c, a, b0, b1);
    }

    float bb0 = b[o0 + g];
    float bb1 = b[o0 + g + 8];
    int n = n0 + nl0;
    *(float2*)(y + (size_t)(o0 + g) * NPOS + n + 2 * tg)     = make_float2(c[0] + bb0, c[1] + bb0);
    *(float2*)(y + (size_t)(o0 + g + 8) * NPOS + n + 2 * tg) = make_float2(c[2] + bb1, c[3] + bb1);
}

// ============================================================
extern "C" void kernel_launch(void* const* d_in, const int* in_sizes, int n_in,
                              void* d_out, int out_size)
{
    const float* x     = (const float*)d_in[0];
    const float* w_qkv = (const float*)d_in[1];
    const float* w_out = (const float*)d_in[2];
    const float* b_out = (const float*)d_in[3];
    float* y = (float*)d_out;

    qkv_kernel<<<dim3(NPOS / 128, 48), 128>>>(x, w_qkv);
    flash_kernel<<<512, 256>>>();
    fused_out_kernel<<<256, 256>>>(w_out, b_out, y);
}

// round 15
// speedup vs baseline: 1.4970x; 1.0876x over previous
#include <cuda_runtime.h>
#include <cuda_bf16.h>

#define HEADS 4
#define DHEAD 32
#define HID 128
#define CIN 64
#define NPOS 4096
#define NSPLIT 8
#define CHUNK (NPOS / NSPLIT) /* 512 */
#define KT 64                 /* keys per smem tile */
#define NTILES (CHUNK / KT)   /* 8 */
#define L2E 1.4426950408889634f
#define OPAD 40               /* sO row pitch (words); conflict-free quads */
#define WPITCH 68             /* qkv smem weight pitch (floats), 4-aligned */

typedef unsigned int uint32;

// ---- device scratch ----
__device__ __align__(16) __nv_bfloat16 g_qtb[HEADS * NPOS * DHEAD]; // [h][n][d], scaled
__device__ __align__(16) __nv_bfloat16 g_ktb[HEADS * NPOS * DHEAD]; // [h][n][d]
__device__ __align__(16) __nv_bfloat16 g_vtb[HEADS * DHEAD * NPOS]; // [h][d][n]
__device__ float g_pm[HEADS * NPOS * NSPLIT];
__device__ float g_pl[HEADS * NPOS * NSPLIT];
__device__ __align__(16) float g_pacc[HEADS * NPOS * NSPLIT * DHEAD];

// m16n8k16 bf16 MMA, fp32 accum, D==C in-place
__device__ __forceinline__ void mma16816(float* d, const uint32* a, uint32 b0, uint32 b1)
{
    asm volatile(
        "mma.sync.aligned.m16n8k16.row.col.f32.bf16.bf16.f32 "
        "{%0,%1,%2,%3},{%4,%5,%6,%7},{%8,%9},{%0,%1,%2,%3};"
        : "+f"(d[0]), "+f"(d[1]), "+f"(d[2]), "+f"(d[3])
        : "r"(a[0]), "r"(a[1]), "r"(a[2]), "r"(a[3]), "r"(b0), "r"(b1));
}

// m16n8k8 tf32 MMA, fp32 accum, D==C in-place
__device__ __forceinline__ void mma1688_tf32(float* d, const uint32* a, uint32 b0, uint32 b1)
{
    asm volatile(
        "mma.sync.aligned.m16n8k8.row.col.f32.tf32.tf32.f32 "
        "{%0,%1,%2,%3},{%4,%5,%6,%7},{%8,%9},{%0,%1,%2,%3};"
        : "+f"(d[0]), "+f"(d[1]), "+f"(d[2]), "+f"(d[3])
        : "r"(a[0]), "r"(a[1]), "r"(a[2]), "r"(a[3]), "r"(b0), "r"(b1));
}

__device__ __forceinline__ uint32 to_tf32(float f)
{
    uint32 r;
    asm("cvt.rna.tf32.f32 %0, %1;" : "=r"(r) : "f"(f));
    return r;
}

__device__ __forceinline__ float ex2(float x)
{
    float y;
    asm("ex2.approx.f32 %0, %1;" : "=f"(y) : "f"(x));
    return y;
}

__device__ __forceinline__ uint32 pk2(float lo, float hi)
{
    __nv_bfloat162 t = __floats2bfloat162_rn(lo, hi);
    return *(uint32*)&t;
}

// ============================================================
// Kernel 1: QKV GEMM, re-tiled. Block 256 = 8 o-groups x 32 n-lanes.
// Thread: 8 o x 4 n. Per c: 1 LDG.128 + 2 broadcast LDS.128 + 32 FFMA.
// grid (32, 6): 128 n x 64 o per block.
// ============================================================
__global__ void __launch_bounds__(256) qkv_kernel(
    const float* __restrict__ x, const float* __restrict__ w)
{
    __shared__ float ws[CIN * WPITCH];   // [c][64 o], pitch 68 -> 17.4 KB

    int tid = threadIdx.x;
    int o0 = blockIdx.y * 64;

    // stage weights transposed: ws[c][oo] = w[o0+oo][c]
    for (int idx = tid; idx < 64 * CIN; idx += 256) {
        int oo = idx >> 6, c = idx & 63;
        ws[c * WPITCH + oo] = w[(size_t)(o0 + oo) * CIN + c];
    }
    __syncthreads();

    int nt = tid & 31;            // n-lane
    int ot = tid >> 5;            // o-group 0..7
    int n = blockIdx.x * 128 + nt * 4;

    float acc[8][4];
#pragma unroll
    for (int k = 0; k < 8; k++)
#pragma unroll
        for (int j = 0; j < 4; j++) acc[k][j] = 0.f;

#pragma unroll 4
    for (int c = 0; c < CIN; c++) {
        float4 xv = *(const float4*)(x + (size_t)c * NPOS + n);
        float4 w0 = *(const float4*)(ws + c * WPITCH + ot * 8);
        float4 w1 = *(const float4*)(ws + c * WPITCH + ot * 8 + 4);
        float wv[8] = {w0.x, w0.y, w0.z, w0.w, w1.x, w1.y, w1.z, w1.w};
#pragma unroll
        for (int k = 0; k < 8; k++) {
            acc[k][0] += wv[k] * xv.x;
            acc[k][1] += wv[k] * xv.y;
            acc[k][2] += wv[k] * xv.z;
            acc[k][3] += wv[k] * xv.w;
        }
    }

    int of = o0 + ot * 8;         // first of 8 consecutive output channels
    int seg = of >> 7;            // 0=q 1=k 2=v (uniform per block)
    int os = of & 127;
    int h = os >> 5, d0 = os & 31;

    if (seg < 2) {
        float scale = (seg == 0) ? 0.17677669529663687f : 1.f;
        __nv_bfloat16* base = (seg == 0 ? g_qtb : g_ktb);
#pragma unroll
        for (int j = 0; j < 4; j++) {
            uint4 pk;
            pk.x = pk2(acc[0][j] * scale, acc[1][j] * scale);
            pk.y = pk2(acc[2][j] * scale, acc[3][j] * scale);
            pk.z = pk2(acc[4][j] * scale, acc[5][j] * scale);
            pk.w = pk2(acc[6][j] * scale, acc[7][j] * scale);
            *(uint4*)(base + (size_t)(h * NPOS + n + j) * DHEAD + d0) = pk;
        }
    } else {
#pragma unroll
        for (int k = 0; k < 8; k++) {
            uint2 pk;
            pk.x = pk2(acc[k][0], acc[k][1]);
            pk.y = pk2(acc[k][2], acc[k][3]);
            *(uint2*)(g_vtb + (size_t)(h * DHEAD + d0 + k) * NPOS + n) = pk;
        }
    }
}

// ============================================================
// Kernel 2: tensor-core flash attention, batched softmax, K/V prefetch.
// grid 1024: bx = h(4) x split(8) x qblk(32). 8 warps x 16 queries.
// ============================================================
__global__ void __launch_bounds__(256) flash_kernel()
{
    __shared__ __nv_bfloat16 sK[KT * 40];      // [64 keys][32 d], rows padded to 80B
    __shared__ __nv_bfloat16 sVt[DHEAD * 72];  // [32 d][64 keys], rows padded to 144B
    uint32* sKu = (uint32*)sK;
    uint32* sVu = (uint32*)sVt;

    int bx = blockIdx.x;
    int qblk = bx & 31, split = (bx >> 5) & 7, h = bx >> 8;
    int tid = threadIdx.x, w = tid >> 5, lane = tid & 31;
    int g = lane >> 2, tg = lane & 3;
    int q0 = qblk * 128 + w * 16;

    uint32 qa[2][4];
    {
        const uint32* Qb = (const uint32*)g_qtb + (size_t)(h * NPOS + q0) * 16;
#pragma unroll
        for (int ks = 0; ks < 2; ks++) {
            qa[ks][0] = Qb[g * 16 + tg + 8 * ks];
            qa[ks][1] = Qb[(g + 8) * 16 + tg + 8 * ks];
            qa[ks][2] = Qb[g * 16 + tg + 4 + 8 * ks];
            qa[ks][3] = Qb[(g + 8) * 16 + tg + 4 + 8 * ks];
        }
    }

    float o[4][4];
#pragma unroll
    for (int a = 0; a < 4; a++)
#pragma unroll
        for (int b = 0; b < 4; b++) o[a][b] = 0.f;
    float m0 = -1e30f, m1 = -1e30f, l0 = 0.f, l1 = 0.f;

    const uint32* Kg = (const uint32*)g_ktb + (size_t)(h * NPOS + split * CHUNK) * 16;
    const uint32* Vg = (const uint32*)g_vtb + (size_t)(h * DHEAD) * (NPOS / 2) + split * (CHUNK / 2);

    int krow_st[4], kcol_st[4], vrow_st[4], vcol_st[4];
#pragma unroll
    for (int it = 0; it < 4; it++) {
        int idx = tid + it * 256;
        krow_st[it] = idx >> 4; kcol_st[it] = idx & 15;
        vrow_st[it] = idx >> 5; vcol_st[it] = idx & 31;
    }

    uint32 pkf[4], pvf[4];
#pragma unroll
    for (int it = 0; it < 4; it++) {
        pkf[it] = Kg[(size_t)krow_st[it] * 16 + kcol_st[it]];
        pvf[it] = Vg[(size_t)vrow_st[it] * (NPOS / 2) + vcol_st[it]];
    }

    for (int tile = 0; tile < NTILES; tile++) {
        __syncthreads();
#pragma unroll
        for (int it = 0; it < 4; it++) {
            sKu[krow_st[it] * 20 + kcol_st[it]] = pkf[it];
            sVu[vrow_st[it] * 36 + vcol_st[it]] = pvf[it];
        }
        __syncthreads();

        if (tile + 1 < NTILES) {
#pragma unroll
            for (int it = 0; it < 4; it++) {
                pkf[it] = Kg[(size_t)((tile + 1) * 64 + krow_st[it]) * 16 + kcol_st[it]];
                pvf[it] = Vg[(size_t)vrow_st[it] * (NPOS / 2) + (tile + 1) * 32 + vcol_st[it]];
            }
        }

        // ---- Phase 1: S MMAs ----
        float sS[4][2][4];
#pragma unroll
        for (int kt = 0; kt < 4; kt++) {
#pragma unroll
            for (int nt = 0; nt < 2; nt++)
#pragma unroll
                for (int c = 0; c < 4; c++) sS[kt][nt][c] = 0.f;
#pragma unroll
            for (int ks = 0; ks < 2; ks++) {
#pragma unroll
                for (int nt = 0; nt < 2; nt++) {
                    int krow = kt * 16 + nt * 8 + g;
                    uint32 b0 = sKu[krow * 20 + tg + 8 * ks];
                    uint32 b1 = sKu[krow * 20 + tg + 4 + 8 * ks];
                    mma16816(sS[kt][nt], qa[ks], b0, b1);
                }
            }
        }

        // ---- Phase 2: one softmax pass ----
        float tm0 = -1e30f, tm1 = -1e30f;
#pragma unroll
        for (int kt = 0; kt < 4; kt++) {
#pragma unroll
            for (int nt = 0; nt < 2; nt++) {
                tm0 = fmaxf(tm0, fmaxf(sS[kt][nt][0], sS[kt][nt][1]));
                tm1 = fmaxf(tm1, fmaxf(sS[kt][nt][2], sS[kt][nt][3]));
            }
        }
        tm0 = fmaxf(tm0, __shfl_xor_sync(0xffffffffu, tm0, 1));
        tm0 = fmaxf(tm0, __shfl_xor_sync(0xffffffffu, tm0, 2));
        tm1 = fmaxf(tm1, __shfl_xor_sync(0xffffffffu, tm1, 1));
        tm1 = fmaxf(tm1, __shfl_xor_sync(0xffffffffu, tm1, 2));
        float nm0 = fmaxf(m0, tm0), nm1 = fmaxf(m1, tm1);
        float c0 = ex2((m0 - nm0) * L2E);
        float c1 = ex2((m1 - nm1) * L2E);
        m0 = nm0; m1 = nm1;
        l0 *= c0; l1 *= c1;
#pragma unroll
        for (int nt = 0; nt < 4; nt++) {
            o[nt][0] *= c0; o[nt][1] *= c0;
            o[nt][2] *= c1; o[nt][3] *= c1;
        }

        // ---- Phase 3: exp + PV MMAs ----
#pragma unroll
        for (int kt = 0; kt < 4; kt++) {
            float p00 = ex2((sS[kt][0][0] - nm0) * L2E);
            float p01 = ex2((sS[kt][0][1] - nm0) * L2E);
            float p10 = ex2((sS[kt][1][0] - nm0) * L2E);
            float p11 = ex2((sS[kt][1][1] - nm0) * L2E);
            float p02 = ex2((sS[kt][0][2] - nm1) * L2E);
            float p03 = ex2((sS[kt][0][3] - nm1) * L2E);
            float p12 = ex2((sS[kt][1][2] - nm1) * L2E);
            float p13 = ex2((sS[kt][1][3] - nm1) * L2E);

            l0 += (p00 + p01) + (p10 + p11);
            l1 += (p02 + p03) + (p12 + p13);

            uint32 pa[4];
            pa[0] = pk2(p00, p01);
            pa[1] = pk2(p02, p03);
            pa[2] = pk2(p10, p11);
            pa[3] = pk2(p12, p13);

#pragma unroll
            for (int nt = 0; nt < 4; nt++) {
                int vrow = nt * 8 + g;
                uint32 b0 = sVu[vrow * 36 + kt * 8 + tg];
                uint32 b1 = sVu[vrow * 36 + kt * 8 + tg + 4];
                mma16816(o[nt], pa, b0, b1);
            }
        }
    }

    l0 += __shfl_xor_sync(0xffffffffu, l0, 1);
    l0 += __shfl_xor_sync(0xffffffffu, l0, 2);
    l1 += __shfl_xor_sync(0xffffffffu, l1, 1);
    l1 += __shfl_xor_sync(0xffffffffu, l1, 2);

    int qg0 = h * NPOS + q0 + g;
    int qg1 = qg0 + 8;
    int pi0 = qg0 * NSPLIT + split;
    int pi1 = qg1 * NSPLIT + split;
    g_pm[pi0] = m0; g_pl[pi0] = l0;
    g_pm[pi1] = m1; g_pl[pi1] = l1;

    float2* P0 = (float2*)(g_pacc + (size_t)pi0 * 32);
    float2* P1 = (float2*)(g_pacc + (size_t)pi1 * 32);
#pragma unroll
    for (int nt = 0; nt < 4; nt++) {
        P0[nt * 4 + tg] = make_float2(o[nt][0], o[nt][1]);
        P1[nt * 4 + tg] = make_float2(o[nt][2], o[nt][3]);
    }
}

// ============================================================
// Kernel 3 (FUSED reduce + outproj): block owns 16 n-positions.
// ============================================================
__global__ void __launch_bounds__(256) fused_out_kernel(
    const float* __restrict__ w, const float* __restrict__ b, float* __restrict__ y)
{
    __shared__ float sO[HID * OPAD];
    int tid = threadIdx.x;
    int n0 = blockIdx.x * 16;

    // ---- Phase A: 64 (h,i) pairs, 4 threads each (8 d's per thread) ----
    {
        int pair = tid >> 2;
        int hh = pair >> 4;
        int il = pair & 15;
        int dq = (tid & 3) * 8;
        int i = n0 + il;
        int base = (hh * NPOS + i) * NSPLIT;

        float pm[NSPLIT], pl[NSPLIT];
#pragma unroll
        for (int s = 0; s < NSPLIT; s++) { pm[s] = g_pm[base + s]; pl[s] = g_pl[base + s]; }
        float M = pm[0];
#pragma unroll
        for (int s = 1; s < NSPLIT; s++) M = fmaxf(M, pm[s]);

        float L = 0.f;
        float num[8];
#pragma unroll
        for (int d = 0; d < 8; d++) num[d] = 0.f;

#pragma unroll
        for (int s = 0; s < NSPLIT; s++) {
            float es = ex2((pm[s] - M) * L2E);
            L += pl[s] * es;
            const float4* pa = (const float4*)(g_pacc + (size_t)(base + s) * 32 + dq);
            float4 a0 = pa[0], a1 = pa[1];
            num[0] += a0.x * es; num[1] += a0.y * es;
            num[2] += a0.z * es; num[3] += a0.w * es;
            num[4] += a1.x * es; num[5] += a1.y * es;
            num[6] += a1.z * es; num[7] += a1.w * es;
        }
        float inv = 1.f / L;
#pragma unroll
        for (int d = 0; d < 8; d++)
            sO[(hh * DHEAD + dq + d) * OPAD + il] = num[d] * inv;
    }
    __syncthreads();

    // ---- Phase B: tf32 MMA ----
    int wp = tid >> 5, lane = tid & 31;
    int g = lane >> 2, tg = lane & 3;
    int ow = wp & 3, nw = wp >> 2;
    int o0 = ow * 16;
    int nl0 = nw * 8;

    float c[4] = {0.f, 0.f, 0.f, 0.f};
    const float* wA0 = w + (size_t)(o0 + g) * HID;
    const float* wA1 = w + (size_t)(o0 + g + 8) * HID;

#pragma unroll
    for (int ks = 0; ks < 16; ks++) {
        int k0 = ks * 8;
        uint32 a[4];
        a[0] = to_tf32(wA0[k0 + tg]);
        a[1] = to_tf32(wA1[k0 + tg]);
        a[2] = to_tf32(wA0[k0 + tg + 4]);
        a[3] = to_tf32(wA1[k0 + tg + 4]);

        uint32 b0 = to_tf32(sO[(k0 + tg) * OPAD + nl0 + g]);
        uint32 b1 = to_tf32(sO[(k0 + tg + 4) * OPAD + nl0 + g]);
        mma1688_tf32(c, a, b0, b1);
    }

    float bb0 = b[o0 + g];
    float bb1 = b[o0 + g + 8];
    int n = n0 + nl0;
    *(float2*)(y + (size_t)(o0 + g) * NPOS + n + 2 * tg)     = make_float2(c[0] + bb0, c[1] + bb0);
    *(float2*)(y + (size_t)(o0 + g + 8) * NPOS + n + 2 * tg) = make_float2(c[2] + bb1, c[3] + bb1);
}

// ============================================================
extern "C" void kernel_launch(void* const* d_in, const int* in_sizes, int n_in,
                              void* d_out, int out_size)
{
    const float* x     = (const float*)d_in[0];
    const float* w_qkv = (const float*)d_in[1];
    const float* w_out = (const float*)d_in[2];
    const float* b_out = (const float*)d_in[3];
    float* y = (float*)d_out;

    qkv_kernel<<<dim3(32, 6), 256>>>(x, w_qkv);
    flash_kernel<<<1024, 256>>>();
    fused_out_kernel<<<256, 256>>>(w_out, b_out, y);
}